// round 1
// baseline (speedup 1.0000x reference)
#include <cuda_runtime.h>

#define BB 512
#define LL 2048
#define CC 64
#define START_S 62
#define STOP_S 63

// scratch (no cudaMalloc allowed)
__device__ float g_expTt[CC * CC];     // [cprime][c] = exp(T[c][cprime])  (transposed)
__device__ float g_eTstop[CC];         // exp(T[c][STOP])
__device__ float g_trow_start[CC];     // T[START][cprime]
__device__ float g_part[BB];
__device__ float g_scores[BB];

// ---------------------------------------------------------------------------
// Precompute exp(T) transposed + boundary vectors.
// ---------------------------------------------------------------------------
__global__ void prep_kernel(const float* __restrict__ T) {
    int i = blockIdx.x * blockDim.x + threadIdx.x;
    if (i < CC * CC) {
        int cp = i >> 6;
        int c  = i & 63;
        g_expTt[i] = __expf(T[c * CC + cp]);   // exp(-10000) -> 0, fine
    }
    if (i < CC) {
        g_eTstop[i]     = __expf(T[i * CC + STOP_S]);
        g_trow_start[i] = T[START_S * CC + i];
    }
}

// ---------------------------------------------------------------------------
// Forward algorithm in exp-space with lagged max renormalization.
// One block (64 threads, 2 warps) per batch. Thread c' owns state c'.
// expT column for c' lives in 64 registers. v double-buffered in shared.
// Invariant at loop top: alpha[c] = log(vsh[cur][c]) + S, with
//   m = max_c v, r = 1/m pending (applied inside next step's w, S += log m).
// ---------------------------------------------------------------------------
__global__ void __launch_bounds__(CC) alpha_kernel(const float* __restrict__ em,
                                                   const float* __restrict__ mask) {
    const int b    = blockIdx.x;
    const int c    = threadIdx.x;
    const int lane = c & 31;
    const int wid  = c >> 5;

    __shared__ __align__(16) float vsh[2][CC];
    __shared__ float smaxb[2][2];
    __shared__ float ssum[2];

    // load my expT column into registers (coalesced-ish, one time)
    float eT[CC];
    {
        const float4* col = reinterpret_cast<const float4*>(&g_expTt[c * CC]);
#pragma unroll
        for (int k = 0; k < CC / 4; ++k) {
            float4 f = col[k];
            eT[4 * k + 0] = f.x;
            eT[4 * k + 1] = f.y;
            eT[4 * k + 2] = f.z;
            eT[4 * k + 3] = f.w;
        }
    }

    const float* emb = em + (size_t)b * (LL * CC);
    const float* mkb = mask + (size_t)b * LL;

    // t = 0: alpha0 = em0 + T[START, :]
    float v = __expf(emb[c] + g_trow_start[c]);   // state 62 -> exp(-1e4) = 0
    float S = 0.0f;
    vsh[0][c] = v;

    float mm = v;
#pragma unroll
    for (int o = 16; o; o >>= 1) mm = fmaxf(mm, __shfl_xor_sync(0xffffffffu, mm, o));
    if (lane == 0) smaxb[0][wid] = mm;
    __syncthreads();
    float m = fmaxf(smaxb[0][0], smaxb[0][1]);
    float r = __fdividef(1.0f, m);

    // software-pipelined emission/mask loads, distance 2
    float em1 = emb[CC + c];
    float mk1 = mkb[1];
    float em2 = emb[2 * CC + c];
    float mk2 = mkb[2];

    int cur = 0;
    for (int t = 1; t < LL; ++t) {
        int tp = t + 2;
        if (tp > LL - 1) tp = LL - 1;
        float emn = emb[tp * CC + c];   // prefetch t+2
        float mkn = mkb[tp];

        float ee = __expf(em1) * r;     // fold renorm into emission factor

        // dot = sum_c vsh[cur][c] * expT[c][c']   (broadcast LDS.128 + reg FMAs)
        const float* vp = vsh[cur];
        float a0 = 0.f, a1 = 0.f, a2 = 0.f, a3 = 0.f;
#pragma unroll
        for (int k = 0; k < CC; k += 4) {
            float4 vv = *reinterpret_cast<const float4*>(vp + k);
            a0 = fmaf(vv.x, eT[k + 0], a0);
            a1 = fmaf(vv.y, eT[k + 1], a1);
            a2 = fmaf(vv.z, eT[k + 2], a2);
            a3 = fmaf(vv.w, eT[k + 3], a3);
        }
        float w  = ((a0 + a1) + (a2 + a3)) * ee;
        float nv = (mk1 > 0.0f) ? w : v * r;    // masked step: pure renorm, alpha kept
        v = nv;

        int nxt = cur ^ 1;
        vsh[nxt][c] = nv;
        S += __logf(m);                 // bookkeeping for the r we just applied

        // max-reduce of new v (result only needed NEXT step -> off chain)
        float x = nv;
#pragma unroll
        for (int o = 16; o; o >>= 1) x = fmaxf(x, __shfl_xor_sync(0xffffffffu, x, o));
        if (lane == 0) smaxb[nxt][wid] = x;
        __syncthreads();
        m = fmaxf(smaxb[nxt][0], smaxb[nxt][1]);
        r = __fdividef(1.0f, m);

        cur = nxt;
        em1 = em2; mk1 = mk2;
        em2 = emn; mk2 = mkn;
    }

    // partition_b = log( sum_c v[c] * exp(T[c,STOP]) ) + S
    float term = v * g_eTstop[c];
#pragma unroll
    for (int o = 16; o; o >>= 1) term += __shfl_xor_sync(0xffffffffu, term, o);
    if (lane == 0) ssum[wid] = term;
    __syncthreads();
    if (c == 0) g_part[b] = __logf(ssum[0] + ssum[1]) + S;
}

// ---------------------------------------------------------------------------
// Gold path score per batch (cheap gathers).
// ---------------------------------------------------------------------------
__global__ void __launch_bounds__(256) scores_kernel(const float* __restrict__ em,
                                                     const float* __restrict__ T,
                                                     const float* __restrict__ mask,
                                                     const int* __restrict__ tags) {
    const int b   = blockIdx.x;
    const int tid = threadIdx.x;
    const float* emb = em + (size_t)b * (LL * CC);
    const float* mkb = mask + (size_t)b * LL;
    const int*   tgb = tags + (size_t)b * LL;

    float acc = 0.f, msum = 0.f;
    for (int t = tid; t < LL; t += 256) {
        msum += mkb[t];
        if (t >= 1) {
            int tg = tgb[t];
            int tq = tgb[t - 1];
            acc += (emb[t * CC + tg] + T[tq * CC + tg]) * mkb[t];
        }
    }

    __shared__ float sacc[8], smsum[8];
#pragma unroll
    for (int o = 16; o; o >>= 1) {
        acc  += __shfl_xor_sync(0xffffffffu, acc, o);
        msum += __shfl_xor_sync(0xffffffffu, msum, o);
    }
    int lane = tid & 31, w = tid >> 5;
    if (lane == 0) { sacc[w] = acc; smsum[w] = msum; }
    __syncthreads();
    if (tid == 0) {
        float A = 0.f, M = 0.f;
#pragma unroll
        for (int i = 0; i < 8; ++i) { A += sacc[i]; M += smsum[i]; }
        int t0 = tgb[0];
        float s = A + emb[t0] + T[START_S * CC + t0];
        int last = (int)M - 1;               // mask sum of 1.0s is exact in fp32
        s += T[tgb[last] * CC + STOP_S];
        g_scores[b] = s;
    }
}

// ---------------------------------------------------------------------------
// mean(partition - scores)
// ---------------------------------------------------------------------------
__global__ void __launch_bounds__(512) finalize_kernel(float* __restrict__ out) {
    int tid = threadIdx.x;
    float d = g_part[tid] - g_scores[tid];
    __shared__ float sh[16];
#pragma unroll
    for (int o = 16; o; o >>= 1) d += __shfl_xor_sync(0xffffffffu, d, o);
    if ((tid & 31) == 0) sh[tid >> 5] = d;
    __syncthreads();
    if (tid < 16) {
        float x = sh[tid];
#pragma unroll
        for (int o = 8; o; o >>= 1) x += __shfl_xor_sync(0x0000ffffu, x, o);
        if (tid == 0) out[0] = x * (1.0f / BB);
    }
}

extern "C" void kernel_launch(void* const* d_in, const int* in_sizes, int n_in,
                              void* d_out, int out_size) {
    (void)in_sizes; (void)n_in; (void)out_size;
    const float* em   = (const float*)d_in[0];
    const float* T    = (const float*)d_in[1];
    const float* mask = (const float*)d_in[2];
    const int*   tags = (const int*)d_in[3];
    float* out = (float*)d_out;

    prep_kernel<<<8, 512>>>(T);
    scores_kernel<<<BB, 256>>>(em, T, mask, tags);
    alpha_kernel<<<BB, CC>>>(em, mask);
    finalize_kernel<<<1, 512>>>(out);
}

// round 2
// speedup vs baseline: 1.5968x; 1.5968x over previous
#include <cuda_runtime.h>

#define BB 512
#define LL 2048
#define CC 64
#define START_S 62
#define STOP_S 63

// scratch (no cudaMalloc allowed)
__device__ float g_expTt[CC * CC];     // [cprime][c] = exp(T[c][cprime])  (transposed)
__device__ float g_eTstop[CC];         // exp(T[c][STOP])
__device__ float g_trow_start[CC];     // T[START][cprime]
__device__ float g_part[BB];
__device__ float g_scores[BB];

// ---------------------------------------------------------------------------
// Precompute exp(T) transposed + boundary vectors.
// ---------------------------------------------------------------------------
__global__ void prep_kernel(const float* __restrict__ T) {
    int i = blockIdx.x * blockDim.x + threadIdx.x;
    if (i < CC * CC) {
        int cp = i >> 6;
        int c  = i & 63;
        g_expTt[i] = __expf(T[c * CC + cp]);   // exp(-10000) -> 0, fine
    }
    if (i < CC) {
        g_eTstop[i]     = __expf(T[i * CC + STOP_S]);
        g_trow_start[i] = T[START_S * CC + i];
    }
}

// half-dot: 32 FMAs, 4 independent chains of depth 8
__device__ __forceinline__ float dot_half(const float* __restrict__ vp,
                                          const float* __restrict__ eT) {
    float a0 = 0.f, a1 = 0.f, a2 = 0.f, a3 = 0.f;
#pragma unroll
    for (int k = 0; k < 32; k += 4) {
        float4 vv = *reinterpret_cast<const float4*>(vp + k);
        a0 = fmaf(vv.x, eT[k + 0], a0);
        a1 = fmaf(vv.y, eT[k + 1], a1);
        a2 = fmaf(vv.z, eT[k + 2], a2);
        a3 = fmaf(vv.w, eT[k + 3], a3);
    }
    return (a0 + a1) + (a2 + a3);
}

// ---------------------------------------------------------------------------
// Forward algorithm in exp-space. One block = one batch, 128 threads.
// Thread (2*cp + h) computes half h of output state cp (split-K=2),
// combined via shfl_xor(1). expT half-column lives in 32 registers.
// Renormalization every 2 steps, pipelined OFF the critical chain:
//   odd step t : launch warp-max shuffle of v (concurrent with the dot)
//   even step  : read block max m, fold r=1/m into emission factor, S += log m
// Invariant: alpha[c] = log(v[c]) + S.
// ---------------------------------------------------------------------------
__global__ void __launch_bounds__(128) alpha_kernel(const float* __restrict__ em,
                                                    const float* __restrict__ mask) {
    const int b    = blockIdx.x;
    const int tid  = threadIdx.x;
    const int h    = tid & 1;         // K-half
    const int cp   = tid >> 1;        // output state 0..63
    const int lane = tid & 31;
    const int wid  = tid >> 5;

    __shared__ __align__(16) float vsh[2][CC];
    __shared__ float smaxb[4];
    __shared__ float ssum[4];

    // my 32 expT coefficients: g_expTt[cp][32h .. 32h+32)
    float eT[32];
    {
        const float4* col = reinterpret_cast<const float4*>(&g_expTt[cp * CC + 32 * h]);
#pragma unroll
        for (int k = 0; k < 8; ++k) {
            float4 f = col[k];
            eT[4 * k + 0] = f.x;
            eT[4 * k + 1] = f.y;
            eT[4 * k + 2] = f.z;
            eT[4 * k + 3] = f.w;
        }
    }

    const float* emb = em + (size_t)b * (LL * CC);
    const float* mkb = mask + (size_t)b * LL;

    // t = 0
    float v = __expf(emb[cp] + g_trow_start[cp]);
    float S = 0.0f;
    if (h == 0) vsh[0][cp] = v;

    // prefetch pipeline, distance 2
    float em1 = emb[CC + cp];
    float mk1 = mkb[1];
    float em2 = emb[2 * CC + cp];
    float mk2 = mkb[2];

    __syncthreads();

    int cur = 0;
    // pairs (odd t, even t+1); t = 1,3,...,2045
#pragma unroll 1
    for (int t = 1; t + 1 < LL; t += 2) {
        // ============ odd step t: reduce-launch ============
        {
            float emn = emb[(size_t)(t + 2) * CC + cp];
            float mkn = mkb[t + 2];

            // warp-max of v (from previous step) — independent of the dot below
            float x = v;
#pragma unroll
            for (int o = 16; o; o >>= 1) x = fmaxf(x, __shfl_xor_sync(0xffffffffu, x, o));
            if (lane == 0) smaxb[wid] = x;

            float ee = __expf(em1);
            float a  = dot_half(vsh[cur] + 32 * h, eT);
            a += __shfl_xor_sync(0xffffffffu, a, 1);
            float nv = (mk1 > 0.f) ? a * ee : v;
            v = nv;
            if (h == 0) vsh[cur ^ 1][cp] = nv;
            __syncthreads();
            cur ^= 1;
            em1 = em2; mk1 = mk2; em2 = emn; mk2 = mkn;
        }
        // ============ even step t+1: apply renorm ============
        {
            int tp = t + 3;
            if (tp > LL - 1) tp = LL - 1;
            float emn = emb[(size_t)tp * CC + cp];
            float mkn = mkb[tp];

            float m = fmaxf(fmaxf(smaxb[0], smaxb[1]), fmaxf(smaxb[2], smaxb[3]));
            float r = __fdividef(1.0f, m);
            S += __logf(m);

            float ee = __expf(em1) * r;
            float a  = dot_half(vsh[cur] + 32 * h, eT);
            a += __shfl_xor_sync(0xffffffffu, a, 1);
            float nv = (mk1 > 0.f) ? a * ee : v * r;
            v = nv;
            if (h == 0) vsh[cur ^ 1][cp] = nv;
            __syncthreads();
            cur ^= 1;
            em1 = em2; mk1 = mk2; em2 = emn; mk2 = mkn;
        }
    }
    // tail step t = LL-1 (odd): plain step, no renorm bookkeeping needed after
    {
        float ee = __expf(em1);
        float a  = dot_half(vsh[cur] + 32 * h, eT);
        a += __shfl_xor_sync(0xffffffffu, a, 1);
        v = (mk1 > 0.f) ? a * ee : v;
    }

    // partition_b = log( sum_c v[c] * exp(T[c,STOP]) ) + S   (count each c once)
    float term = (h == 0) ? v * g_eTstop[cp] : 0.0f;
#pragma unroll
    for (int o = 16; o; o >>= 1) term += __shfl_xor_sync(0xffffffffu, term, o);
    if (lane == 0) ssum[wid] = term;
    __syncthreads();
    if (tid == 0)
        g_part[b] = __logf(((ssum[0] + ssum[1]) + (ssum[2] + ssum[3]))) + S;
}

// ---------------------------------------------------------------------------
// Gold path score per batch (cheap gathers).
// ---------------------------------------------------------------------------
__global__ void __launch_bounds__(256) scores_kernel(const float* __restrict__ em,
                                                     const float* __restrict__ T,
                                                     const float* __restrict__ mask,
                                                     const int* __restrict__ tags) {
    const int b   = blockIdx.x;
    const int tid = threadIdx.x;
    const float* emb = em + (size_t)b * (LL * CC);
    const float* mkb = mask + (size_t)b * LL;
    const int*   tgb = tags + (size_t)b * LL;

    float acc = 0.f, msum = 0.f;
    for (int t = tid; t < LL; t += 256) {
        msum += mkb[t];
        if (t >= 1) {
            int tg = tgb[t];
            int tq = tgb[t - 1];
            acc += (emb[(size_t)t * CC + tg] + T[tq * CC + tg]) * mkb[t];
        }
    }

    __shared__ float sacc[8], smsum[8];
#pragma unroll
    for (int o = 16; o; o >>= 1) {
        acc  += __shfl_xor_sync(0xffffffffu, acc, o);
        msum += __shfl_xor_sync(0xffffffffu, msum, o);
    }
    int lane = tid & 31, w = tid >> 5;
    if (lane == 0) { sacc[w] = acc; smsum[w] = msum; }
    __syncthreads();
    if (tid == 0) {
        float A = 0.f, M = 0.f;
#pragma unroll
        for (int i = 0; i < 8; ++i) { A += sacc[i]; M += smsum[i]; }
        int t0 = tgb[0];
        float s = A + emb[t0] + T[START_S * CC + t0];
        int last = (int)M - 1;               // mask sum of 1.0s is exact in fp32
        s += T[tgb[last] * CC + STOP_S];
        g_scores[b] = s;
    }
}

// ---------------------------------------------------------------------------
// mean(partition - scores)
// ---------------------------------------------------------------------------
__global__ void __launch_bounds__(512) finalize_kernel(float* __restrict__ out) {
    int tid = threadIdx.x;
    float d = g_part[tid] - g_scores[tid];
    __shared__ float sh[16];
#pragma unroll
    for (int o = 16; o; o >>= 1) d += __shfl_xor_sync(0xffffffffu, d, o);
    if ((tid & 31) == 0) sh[tid >> 5] = d;
    __syncthreads();
    if (tid < 16) {
        float x = sh[tid];
#pragma unroll
        for (int o = 8; o; o >>= 1) x += __shfl_xor_sync(0x0000ffffu, x, o);
        if (tid == 0) out[0] = x * (1.0f / BB);
    }
}

extern "C" void kernel_launch(void* const* d_in, const int* in_sizes, int n_in,
                              void* d_out, int out_size) {
    (void)in_sizes; (void)n_in; (void)out_size;
    const float* em   = (const float*)d_in[0];
    const float* T    = (const float*)d_in[1];
    const float* mask = (const float*)d_in[2];
    const int*   tags = (const int*)d_in[3];
    float* out = (float*)d_out;

    prep_kernel<<<8, 512>>>(T);
    scores_kernel<<<BB, 256>>>(em, T, mask, tags);
    alpha_kernel<<<BB, 128>>>(em, mask);
    finalize_kernel<<<1, 512>>>(out);
}

// round 3
// speedup vs baseline: 1.9656x; 1.2310x over previous
#include <cuda_runtime.h>

#define BB 512
#define LL 2048
#define CC 64
#define START_S 62
#define STOP_S 63

// scratch (no cudaMalloc allowed)
__device__ float g_expTt[CC * CC];     // [cprime][c] = exp(T[c][cprime])  (transposed)
__device__ float g_eTstop[CC];         // exp(T[c][STOP])
__device__ float g_trow_start[CC];     // T[START][cprime]
__device__ float g_part[BB];
__device__ float g_scores[BB];

typedef unsigned long long u64;

// packed fp32x2 FMA (sm_100+ PTX only; ptxas never emits this from C++)
__device__ __forceinline__ u64 fma2(u64 a, u64 b, u64 c) {
    u64 d;
    asm("fma.rn.f32x2 %0, %1, %2, %3;" : "=l"(d) : "l"(a), "l"(b), "l"(c));
    return d;
}
__device__ __forceinline__ float sum2(u64 a) {
    float lo, hi;
    asm("mov.b64 {%0,%1}, %2;" : "=f"(lo), "=f"(hi) : "l"(a));
    return lo + hi;
}

// ---------------------------------------------------------------------------
// Precompute exp(T) transposed + boundary vectors.
// ---------------------------------------------------------------------------
__global__ void prep_kernel(const float* __restrict__ T) {
    int i = blockIdx.x * blockDim.x + threadIdx.x;
    if (i < CC * CC) {
        int cp = i >> 6;
        int c  = i & 63;
        g_expTt[i] = __expf(T[c * CC + cp]);   // exp(-10000) -> 0, fine
    }
    if (i < CC) {
        g_eTstop[i]     = __expf(T[i * CC + STOP_S]);
        g_trow_start[i] = T[START_S * CC + i];
    }
}

// full 64-dot in packed fp32x2: 32 FFMA2, 4 independent chains of depth 8
__device__ __forceinline__ float dot64(const float* __restrict__ vsrc,
                                       const u64* __restrict__ eT) {
    const ulonglong2* vp = reinterpret_cast<const ulonglong2*>(vsrc);
    u64 a0 = 0, a1 = 0, a2 = 0, a3 = 0;   // 0x0 == packed {0.f,0.f}
#pragma unroll
    for (int k = 0; k < 16; k += 2) {
        ulonglong2 v0 = vp[k];
        ulonglong2 v1 = vp[k + 1];
        a0 = fma2(v0.x, eT[2 * k + 0], a0);
        a1 = fma2(v0.y, eT[2 * k + 1], a1);
        a2 = fma2(v1.x, eT[2 * k + 2], a2);
        a3 = fma2(v1.y, eT[2 * k + 3], a3);
    }
    return (sum2(a0) + sum2(a1)) + (sum2(a2) + sum2(a3));
}

// ---------------------------------------------------------------------------
// Forward algorithm in exp-space. One block = one batch, 64 threads (2 warps).
// Thread cp owns output state cp; its exp(T) column lives in 32 packed-b64
// registers, consumed by fma.rn.f32x2 (2 fp32 MACs per issue slot).
// Renormalization every 2 steps, pipelined OFF the critical chain:
//   odd step t : launch warp-max shuffle of v (concurrent with the dot)
//   even step  : fold r = 1/max into the emission factor, S += log(max)
// Invariant: alpha[c] = log(v[c]) + S.
// ---------------------------------------------------------------------------
__global__ void __launch_bounds__(CC) alpha_kernel(const float* __restrict__ em,
                                                   const float* __restrict__ mask) {
    const int b    = blockIdx.x;
    const int cp   = threadIdx.x;
    const int lane = cp & 31;
    const int wid  = cp >> 5;

    __shared__ __align__(16) float vsh[2][CC];
    __shared__ float smaxb[2];
    __shared__ float ssum[2];

    // my exp(T) column, packed pairs
    u64 eT[32];
    {
        const ulonglong2* col = reinterpret_cast<const ulonglong2*>(&g_expTt[cp * CC]);
#pragma unroll
        for (int k = 0; k < 16; ++k) {
            ulonglong2 q = col[k];
            eT[2 * k + 0] = q.x;
            eT[2 * k + 1] = q.y;
        }
    }

    const float* emb = em + (size_t)b * (LL * CC);
    const float* mkb = mask + (size_t)b * LL;

    // t = 0
    float v = __expf(emb[cp] + g_trow_start[cp]);
    float S = 0.0f;
    vsh[0][cp] = v;

    // prefetch pipeline, distance 2
    float em1 = emb[CC + cp];
    float mk1 = mkb[1];
    float em2 = emb[2 * CC + cp];
    float mk2 = mkb[2];

    __syncthreads();

    int cur = 0;
#pragma unroll 1
    for (int t = 1; t + 1 < LL; t += 2) {
        // ============ odd step t: launch the max-reduce ============
        {
            float emn = emb[(size_t)(t + 2) * CC + cp];
            float mkn = mkb[t + 2];

            // warp-max of previous v — independent of the dot below
            float x = v;
#pragma unroll
            for (int o = 16; o; o >>= 1) x = fmaxf(x, __shfl_xor_sync(0xffffffffu, x, o));
            if (lane == 0) smaxb[wid] = x;

            float ee = __expf(em1);
            float a  = dot64(vsh[cur], eT);
            float nv = (mk1 > 0.f) ? a * ee : v;
            v = nv;
            vsh[cur ^ 1][cp] = nv;
            __syncthreads();
            cur ^= 1;
            em1 = em2; mk1 = mk2; em2 = emn; mk2 = mkn;
        }
        // ============ even step t+1: apply renorm ============
        {
            int tp = t + 3;
            if (tp > LL - 1) tp = LL - 1;
            float emn = emb[(size_t)tp * CC + cp];
            float mkn = mkb[tp];

            float m = fmaxf(smaxb[0], smaxb[1]);
            float r = __fdividef(1.0f, m);
            S += __logf(m);

            float ee = __expf(em1) * r;
            float a  = dot64(vsh[cur], eT);
            float nv = (mk1 > 0.f) ? a * ee : v * r;
            v = nv;
            vsh[cur ^ 1][cp] = nv;
            __syncthreads();
            cur ^= 1;
            em1 = em2; mk1 = mk2; em2 = emn; mk2 = mkn;
        }
    }
    // tail step t = LL-1 (odd)
    {
        float ee = __expf(em1);
        float a  = dot64(vsh[cur], eT);
        v = (mk1 > 0.f) ? a * ee : v;
    }

    // partition_b = log( sum_c v[c] * exp(T[c,STOP]) ) + S
    float term = v * g_eTstop[cp];
#pragma unroll
    for (int o = 16; o; o >>= 1) term += __shfl_xor_sync(0xffffffffu, term, o);
    if (lane == 0) ssum[wid] = term;
    __syncthreads();
    if (cp == 0) g_part[b] = __logf(ssum[0] + ssum[1]) + S;
}

// ---------------------------------------------------------------------------
// Gold path score per batch (cheap gathers).
// ---------------------------------------------------------------------------
__global__ void __launch_bounds__(256) scores_kernel(const float* __restrict__ em,
                                                     const float* __restrict__ T,
                                                     const float* __restrict__ mask,
                                                     const int* __restrict__ tags) {
    const int b   = blockIdx.x;
    const int tid = threadIdx.x;
    const float* emb = em + (size_t)b * (LL * CC);
    const float* mkb = mask + (size_t)b * LL;
    const int*   tgb = tags + (size_t)b * LL;

    float acc = 0.f, msum = 0.f;
    for (int t = tid; t < LL; t += 256) {
        msum += mkb[t];
        if (t >= 1) {
            int tg = tgb[t];
            int tq = tgb[t - 1];
            acc += (emb[(size_t)t * CC + tg] + T[tq * CC + tg]) * mkb[t];
        }
    }

    __shared__ float sacc[8], smsum[8];
#pragma unroll
    for (int o = 16; o; o >>= 1) {
        acc  += __shfl_xor_sync(0xffffffffu, acc, o);
        msum += __shfl_xor_sync(0xffffffffu, msum, o);
    }
    int lane = tid & 31, w = tid >> 5;
    if (lane == 0) { sacc[w] = acc; smsum[w] = msum; }
    __syncthreads();
    if (tid == 0) {
        float A = 0.f, M = 0.f;
#pragma unroll
        for (int i = 0; i < 8; ++i) { A += sacc[i]; M += smsum[i]; }
        int t0 = tgb[0];
        float s = A + emb[t0] + T[START_S * CC + t0];
        int last = (int)M - 1;               // mask sum of 1.0s is exact in fp32
        s += T[tgb[last] * CC + STOP_S];
        g_scores[b] = s;
    }
}

// ---------------------------------------------------------------------------
// mean(partition - scores)
// ---------------------------------------------------------------------------
__global__ void __launch_bounds__(512) finalize_kernel(float* __restrict__ out) {
    int tid = threadIdx.x;
    float d = g_part[tid] - g_scores[tid];
    __shared__ float sh[16];
#pragma unroll
    for (int o = 16; o; o >>= 1) d += __shfl_xor_sync(0xffffffffu, d, o);
    if ((tid & 31) == 0) sh[tid >> 5] = d;
    __syncthreads();
    if (tid < 16) {
        float x = sh[tid];
#pragma unroll
        for (int o = 8; o; o >>= 1) x += __shfl_xor_sync(0x0000ffffu, x, o);
        if (tid == 0) out[0] = x * (1.0f / BB);
    }
}

extern "C" void kernel_launch(void* const* d_in, const int* in_sizes, int n_in,
                              void* d_out, int out_size) {
    (void)in_sizes; (void)n_in; (void)out_size;
    const float* em   = (const float*)d_in[0];
    const float* T    = (const float*)d_in[1];
    const float* mask = (const float*)d_in[2];
    const int*   tags = (const int*)d_in[3];
    float* out = (float*)d_out;

    prep_kernel<<<8, 512>>>(T);
    scores_kernel<<<BB, 256>>>(em, T, mask, tags);
    alpha_kernel<<<BB, CC>>>(em, mask);
    finalize_kernel<<<1, 512>>>(out);
}